// round 11
// baseline (speedup 1.0000x reference)
#include <cuda_runtime.h>
#include <cuda_bf16.h>
#include <cstdint>

// Problem constants (fixed shapes)
constexpr int BATCH  = 8;
constexpr int SEQ    = 4096;
constexpr int NODES  = BATCH * SEQ;     // 32768 = 2^15
constexpr int HD     = 128;
constexpr int NE     = 524288;
constexpr int RELS   = 8;
constexpr int LAYERS = 2;
constexpr int NMAT   = RELS + 1;        // 8 rel + 1 self per layer
constexpr int TOTW   = LAYERS * NMAT + 1;  // + proj = 19 split matrices

// Scratch (device globals; no dynamic allocation allowed)
__device__ float g_x[(size_t)NODES * HD];            // node states
__device__ float g_y[(size_t)RELS * NODES * HD];     // per-relation x@Wr^T
__device__ float g_self[(size_t)NODES * HD];         // x@Ws^T + b
__device__ __nv_bfloat16 g_xhi[(size_t)NODES * HD];  // split node states
__device__ __nv_bfloat16 g_xlo[(size_t)NODES * HD];
__device__ __nv_bfloat16 g_whi[(size_t)TOTW * HD * HD];  // [l][j] then proj last
__device__ __nv_bfloat16 g_wlo[(size_t)TOTW * HD * HD];
// CSR by dst
__device__ int g_cnt[NODES];
__device__ int g_cur[NODES];
__device__ int g_off[NODES + 1];
__device__ int g_eid[NE];                // (rel << 15) | src

// ---------------------------------------------------------------------------
// PTX helpers (arch-agnostic: ldmatrix / mma.sync / cp.async, sm_80+)
// ---------------------------------------------------------------------------
__device__ __forceinline__ uint32_t smem_u32(const void* p) {
    uint32_t a;
    asm("{ .reg .u64 t; cvta.to.shared.u64 t, %1; cvt.u32.u64 %0, t; }"
        : "=r"(a) : "l"(p));
    return a;
}
__device__ __forceinline__ void ldsm_x4(uint32_t* r, uint32_t addr) {
    asm volatile("ldmatrix.sync.aligned.m8n8.x4.shared.b16 {%0,%1,%2,%3}, [%4];"
                 : "=r"(r[0]), "=r"(r[1]), "=r"(r[2]), "=r"(r[3]) : "r"(addr));
}
__device__ __forceinline__ void ldsm_x2(uint32_t* r, uint32_t addr) {
    asm volatile("ldmatrix.sync.aligned.m8n8.x2.shared.b16 {%0,%1}, [%2];"
                 : "=r"(r[0]), "=r"(r[1]) : "r"(addr));
}
__device__ __forceinline__ void mma16816(float* d, const uint32_t* a, const uint32_t* b) {
    asm volatile(
        "mma.sync.aligned.m16n8k16.row.col.f32.bf16.bf16.f32 "
        "{%0,%1,%2,%3}, {%4,%5,%6,%7}, {%8,%9}, {%0,%1,%2,%3};"
        : "+f"(d[0]), "+f"(d[1]), "+f"(d[2]), "+f"(d[3])
        : "r"(a[0]), "r"(a[1]), "r"(a[2]), "r"(a[3]), "r"(b[0]), "r"(b[1]));
}
__device__ __forceinline__ void cp_async16(uint32_t daddr, const void* src) {
    asm volatile("cp.async.ca.shared.global [%0], [%1], 16;"
                 :: "r"(daddr), "l"(src));
}
__device__ __forceinline__ void cp_commit() {
    asm volatile("cp.async.commit_group;" ::: "memory");
}
template <int N>
__device__ __forceinline__ void cp_wait() {
    asm volatile("cp.async.wait_group %0;" :: "n"(N) : "memory");
}

__device__ __forceinline__ void split2(float v0, float v1,
                                       __nv_bfloat162& hi, __nv_bfloat162& lo) {
    __nv_bfloat16 h0 = __float2bfloat16(v0);
    __nv_bfloat16 h1 = __float2bfloat16(v1);
    hi = __halves2bfloat162(h0, h1);
    lo = __halves2bfloat162(__float2bfloat16(v0 - __bfloat162float(h0)),
                            __float2bfloat16(v1 - __bfloat162float(h1)));
}

// ---------------------------------------------------------------------------
// CSR build kernels
// ---------------------------------------------------------------------------
__global__ void k_zero_cnt() {
    int i = blockIdx.x * blockDim.x + threadIdx.x;
    g_cnt[i] = 0;
    g_cur[i] = 0;
}
__global__ void k_count(const int* __restrict__ dst) {
    int e = blockIdx.x * blockDim.x + threadIdx.x;
    atomicAdd(&g_cnt[dst[e]], 1);
}
// single-block exclusive scan of g_cnt (32768 ints, 1024 threads x 32 each)
__global__ void k_scan() {
    __shared__ int warp_sums[32];
    int t = threadIdx.x;
    int base = t * 32;
    int local[32];
    int sum = 0;
#pragma unroll
    for (int i = 0; i < 32; i++) { local[i] = sum; sum += g_cnt[base + i]; }
    int lane = t & 31, w = t >> 5;
    int v = sum;
#pragma unroll
    for (int d = 1; d < 32; d <<= 1) {
        int n = __shfl_up_sync(0xFFFFFFFF, v, d);
        if (lane >= d) v += n;
    }
    if (lane == 31) warp_sums[w] = v;
    __syncthreads();
    if (w == 0) {
        int x = warp_sums[lane];
#pragma unroll
        for (int d = 1; d < 32; d <<= 1) {
            int n = __shfl_up_sync(0xFFFFFFFF, x, d);
            if (lane >= d) x += n;
        }
        warp_sums[lane] = x;
    }
    __syncthreads();
    int excl = v - sum + (w > 0 ? warp_sums[w - 1] : 0);
#pragma unroll
    for (int i = 0; i < 32; i++) g_off[base + i] = excl + local[i];
    if (t == 1023) g_off[NODES] = excl + sum;   // == NE
}
__global__ void k_fill(const int* __restrict__ src, const int* __restrict__ dst,
                       const int* __restrict__ et) {
    int e = blockIdx.x * blockDim.x + threadIdx.x;
    int d = dst[e];
    int p = atomicAdd(&g_cur[d], 1);
    g_eid[g_off[d] + p] = (et[e] << 15) | src[e];
}

// split weights: mats 0..17 = [l][j(0..8)] (j==8 self), mat 18 = proj_W
__global__ void k_split_w(const float* __restrict__ relW, const float* __restrict__ selfW,
                          const float* __restrict__ projW) {
    int t = blockIdx.x * blockDim.x + threadIdx.x;   // TOTW*HD*HD threads
    int mat = t / (HD * HD);
    int pos = t % (HD * HD);
    float v;
    if (mat < LAYERS * NMAT) {
        int l = mat / NMAT, j = mat % NMAT;
        v = (j < RELS) ? relW[(size_t)(l * RELS + j) * HD * HD + pos]
                       : selfW[(size_t)l * HD * HD + pos];
    } else {
        v = projW[pos];
    }
    __nv_bfloat16 h = __float2bfloat16(v);
    g_whi[t] = h;
    g_wlo[t] = __float2bfloat16(v - __bfloat162float(h));
}

// ---------------------------------------------------------------------------
// Tensor-core GEMM building blocks (warp tile 64x32, 8 warps, tile 128x128)
// ---------------------------------------------------------------------------
constexpr int LDT    = 136;              // padded bf16 row stride (272 B)
constexpr int TILE_E = 128 * LDT;        // bf16 elems per tile (17408)

// 3-term (hi*hi + hi*lo + lo*hi) 128x128x128 mma into d[4][4][4]
__device__ __forceinline__ void mma_tile(float d[4][4][4],
                                         uint32_t aAhi, uint32_t aAlo,
                                         uint32_t aWhi, uint32_t aWlo,
                                         int mw, int nw, int lane) {
    const int a_row  = lane & 15;
    const int a_koff = (lane >> 4) * 8;
    const int b_row  = lane & 7;
    const int b_koff = ((lane >> 3) & 1) * 8;
#pragma unroll
    for (int term = 0; term < 3; term++) {
        const uint32_t aA = (term == 2) ? aAlo : aAhi;
        const uint32_t aW = (term == 1) ? aWlo : aWhi;
#pragma unroll
        for (int k0 = 0; k0 < 128; k0 += 16) {
            uint32_t afr[4][4], bfr[4][2];
#pragma unroll
            for (int mi = 0; mi < 4; mi++)
                ldsm_x4(afr[mi], aA + ((mw + mi * 16 + a_row) * LDT + k0 + a_koff) * 2);
#pragma unroll
            for (int ni = 0; ni < 4; ni++)
                ldsm_x2(bfr[ni], aW + ((nw + ni * 8 + b_row) * LDT + k0 + b_koff) * 2);
#pragma unroll
            for (int mi = 0; mi < 4; mi++)
#pragma unroll
                for (int ni = 0; ni < 4; ni++)
                    mma16816(d[mi][ni], afr[mi], bfr[ni]);
        }
    }
}

// ---------------------------------------------------------------------------
// Embed + projection via mma: A = split(cemb[cid]+kemb[kid]); out = bf16 splits of
// A @ proj_W^T + proj_b  (writes g_xhi/g_xlo only)
// ---------------------------------------------------------------------------
constexpr int EMB_SMEM = 4 * TILE_E * 2;      // 139264 B

__global__ __launch_bounds__(256, 1)
void k_embed(const int* __restrict__ cids, const int* __restrict__ kids,
             const float* __restrict__ cemb, const float* __restrict__ kemb,
             const float* __restrict__ bias) {
    extern __shared__ __nv_bfloat16 sm[];
    __nv_bfloat16* sAhi = sm;
    __nv_bfloat16* sAlo = sm + TILE_E;
    __nv_bfloat16* sWhi = sm + 2 * TILE_E;
    __nv_bfloat16* sWlo = sm + 3 * TILE_E;

    const int tid  = threadIdx.x;
    const int wid  = tid >> 5;
    const int lane = tid & 31;
    const int m0   = blockIdx.x * 128;
    const int mw   = (wid >> 2) * 64;
    const int nw   = (wid & 3) * 32;

    // A fill: thread -> (row, half of 64 cols); gather + add + split
    {
        int row = tid >> 1, half = tid & 1;
        int node = m0 + row;
        const float4* cp = (const float4*)(cemb + (size_t)cids[node] * HD + half * 64);
        const float4* kp = (const float4*)(kemb + (size_t)kids[node] * HD + half * 64);
        int eb = row * LDT + half * 64;
#pragma unroll
        for (int c = 0; c < 16; c++) {
            float4 a = cp[c], b = kp[c];
            __nv_bfloat162 h0, l0, h1, l1;
            split2(a.x + b.x, a.y + b.y, h0, l0);
            split2(a.z + b.z, a.w + b.w, h1, l1);
            *(__nv_bfloat162*)(sAhi + eb + c * 4)     = h0;
            *(__nv_bfloat162*)(sAhi + eb + c * 4 + 2) = h1;
            *(__nv_bfloat162*)(sAlo + eb + c * 4)     = l0;
            *(__nv_bfloat162*)(sAlo + eb + c * 4 + 2) = l1;
        }
    }
    // W fill (proj = mat TOTW-1)
    {
        int row = tid >> 1, half = tid & 1;
        const uint4* wh = (const uint4*)(g_whi + (size_t)(TOTW - 1) * HD * HD
                                         + (size_t)row * HD + half * 64);
        const uint4* wl = (const uint4*)(g_wlo + (size_t)(TOTW - 1) * HD * HD
                                         + (size_t)row * HD + half * 64);
        int eb = row * LDT + half * 64;
#pragma unroll
        for (int c = 0; c < 8; c++) {
            *(uint4*)(sWhi + eb + c * 8) = wh[c];
            *(uint4*)(sWlo + eb + c * 8) = wl[c];
        }
    }
    __syncthreads();

    float d[4][4][4];
#pragma unroll
    for (int mi = 0; mi < 4; mi++)
#pragma unroll
        for (int ni = 0; ni < 4; ni++)
#pragma unroll
            for (int q = 0; q < 4; q++) d[mi][ni][q] = 0.0f;

    mma_tile(d, smem_u32(sAhi), smem_u32(sAlo), smem_u32(sWhi), smem_u32(sWlo),
             mw, nw, lane);

    // epilogue: split and store g_xhi / g_xlo
#pragma unroll
    for (int mi = 0; mi < 4; mi++) {
        int r0 = mw + mi * 16 + (lane >> 2);
#pragma unroll
        for (int ni = 0; ni < 4; ni++) {
            int c = nw + ni * 8 + (lane & 3) * 2;
            float b0 = bias[c], b1 = bias[c + 1];
            __nv_bfloat162 h, lo;
            size_t p0 = (size_t)(m0 + r0) * HD + c;
            split2(d[mi][ni][0] + b0, d[mi][ni][1] + b1, h, lo);
            *(__nv_bfloat162*)(g_xhi + p0) = h;
            *(__nv_bfloat162*)(g_xlo + p0) = lo;
            size_t p1 = (size_t)(m0 + r0 + 8) * HD + c;
            split2(d[mi][ni][2] + b0, d[mi][ni][3] + b1, h, lo);
            *(__nv_bfloat162*)(g_xhi + p1) = h;
            *(__nv_bfloat162*)(g_xlo + p1) = lo;
        }
    }
}

// ---------------------------------------------------------------------------
// Persistent layer GEMM: 2304 units (256 m-tiles x 9 mats), grid=148 CTAs,
// contiguous unit ranges (A reused across j), cp.async double-buffered W.
// ---------------------------------------------------------------------------
constexpr int GRID_GEMM = 148;
constexpr int NUNITS    = (NODES / 128) * NMAT;       // 2304
constexpr int GEMM_SMEM = (2 * TILE_E + 4 * TILE_E) * 2;  // 208896 B

__global__ __launch_bounds__(256, 1)
void k_gemm(const float* __restrict__ selfb, int l) {
    extern __shared__ __nv_bfloat16 sm[];
    __nv_bfloat16* sAhi = sm;
    __nv_bfloat16* sAlo = sm + TILE_E;
    __nv_bfloat16* sWst = sm + 2 * TILE_E;   // [stage][hi|lo][TILE_E]

    const int tid  = threadIdx.x;
    const int wid  = tid >> 5;
    const int lane = tid & 31;
    const int mw   = (wid >> 2) * 64;
    const int nw   = (wid & 3) * 32;

    const int u0 = (int)(((long)blockIdx.x * NUNITS) / GRID_GEMM);
    const int u1 = (int)(((long)(blockIdx.x + 1) * NUNITS) / GRID_GEMM);

    const int frow = tid >> 1, fhalf = tid & 1;        // fill-thread mapping
    const uint32_t wst_base = smem_u32(sWst);

    auto fillW = [&](int u, int stage) {
        int j = u % NMAT;
        size_t wb = (size_t)(l * NMAT + j) * HD * HD + (size_t)frow * HD + fhalf * 64;
        uint32_t dh = wst_base + (uint32_t)(stage * 2 * TILE_E + frow * LDT + fhalf * 64) * 2;
        uint32_t dl = dh + TILE_E * 2;
        const __nv_bfloat16* sh = g_whi + wb;
        const __nv_bfloat16* sl = g_wlo + wb;
#pragma unroll
        for (int c = 0; c < 8; c++) {
            cp_async16(dh + c * 16, sh + c * 8);
            cp_async16(dl + c * 16, sl + c * 8);
        }
    };

    // prologue: prefetch W of first unit into stage 0
    fillW(u0, 0);
    cp_commit();

    int cur_m = -1;
    int s = 0;
    for (int u = u0; u < u1; u++) {
        int m = u / NMAT, j = u % NMAT;
        __syncthreads();   // prior reads of A and buf[1-s] complete
        if (m != cur_m) {
            int m0f = m * 128;
            size_t xb = (size_t)(m0f + frow) * HD + fhalf * 64;
            const uint4* xh = (const uint4*)(g_xhi + xb);
            const uint4* xl = (const uint4*)(g_xlo + xb);
            int eb = frow * LDT + fhalf * 64;
#pragma unroll
            for (int c = 0; c < 8; c++) {
                *(uint4*)(sAhi + eb + c * 8) = xh[c];
                *(uint4*)(sAlo + eb + c * 8) = xl[c];
            }
            cur_m = m;
        }
        if (u + 1 < u1) {
            fillW(u + 1, 1 - s);
            cp_commit();
            cp_wait<1>();    // W[u] (older group) complete
        } else {
            cp_wait<0>();
        }
        __syncthreads();     // W[u] + A visible to all warps

        float d[4][4][4];
#pragma unroll
        for (int mi = 0; mi < 4; mi++)
#pragma unroll
            for (int ni = 0; ni < 4; ni++)
#pragma unroll
                for (int q = 0; q < 4; q++) d[mi][ni][q] = 0.0f;

        uint32_t wh = wst_base + (uint32_t)(s * 2 * TILE_E) * 2;
        uint32_t wl = wh + TILE_E * 2;
        mma_tile(d, smem_u32(sAhi), smem_u32(sAlo), wh, wl, mw, nw, lane);

        // epilogue
        int m0f = m * 128;
        float* C = (j < RELS) ? g_y + ((size_t)j * NODES + m0f) * HD
                              : g_self + (size_t)m0f * HD;
#pragma unroll
        for (int mi = 0; mi < 4; mi++) {
            int r0 = mw + mi * 16 + (lane >> 2);
#pragma unroll
            for (int ni = 0; ni < 4; ni++) {
                int c = nw + ni * 8 + (lane & 3) * 2;
                float b0 = 0.0f, b1 = 0.0f;
                if (j == RELS) {
                    b0 = selfb[l * HD + c];
                    b1 = selfb[l * HD + c + 1];
                }
                *(float2*)(C + (size_t)r0 * HD + c) =
                    make_float2(d[mi][ni][0] + b0, d[mi][ni][1] + b1);
                *(float2*)(C + (size_t)(r0 + 8) * HD + c) =
                    make_float2(d[mi][ni][2] + b0, d[mi][ni][3] + b1);
            }
        }
        s ^= 1;
    }
}

// ---------------------------------------------------------------------------
// Fused CSR aggregate + deg-normalize + ReLU + bf16 split. One warp per node.
// ---------------------------------------------------------------------------
__global__ __launch_bounds__(256)
void k_agg_update() {
    const int wid  = threadIdx.x >> 5;
    const int lane = threadIdx.x & 31;
    const int node = blockIdx.x * 8 + wid;
    const int s0 = g_off[node], s1 = g_off[node + 1];

    float4 acc = make_float4(0.f, 0.f, 0.f, 0.f);
    int k = s0;
    if (k < s1) {
        int p = g_eid[k];
        for (; k < s1; ) {
            const float4* row =
                (const float4*)(g_y + ((size_t)(p >> 15) * NODES + (p & 32767)) * HD);
            int pn = (k + 1 < s1) ? g_eid[k + 1] : 0;   // prefetch next id
            float4 v = row[lane];
            acc.x += v.x; acc.y += v.y; acc.z += v.z; acc.w += v.w;
            p = pn;
            k++;
        }
    }
    float invd = 1.0f / fmaxf((float)(s1 - s0), 1.0f);
    size_t base = (size_t)node * HD + lane * 4;
    float4 sf = *(const float4*)(g_self + base);
    float4 o;
    o.x = fmaxf(fmaf(acc.x, invd, sf.x), 0.0f);
    o.y = fmaxf(fmaf(acc.y, invd, sf.y), 0.0f);
    o.z = fmaxf(fmaf(acc.z, invd, sf.z), 0.0f);
    o.w = fmaxf(fmaf(acc.w, invd, sf.w), 0.0f);
    *(float4*)(g_x + base) = o;

    __nv_bfloat162 h0, l0, h1, l1;
    split2(o.x, o.y, h0, l0);
    split2(o.z, o.w, h1, l1);
    *(__nv_bfloat162*)(g_xhi + base)     = h0;
    *(__nv_bfloat162*)(g_xhi + base + 2) = h1;
    *(__nv_bfloat162*)(g_xlo + base)     = l0;
    *(__nv_bfloat162*)(g_xlo + base + 2) = l1;
}

__global__ void k_output(const int* __restrict__ mask, float* __restrict__ out) {
    int t = blockIdx.x * blockDim.x + threadIdx.x;  // grid covers NODES*HD/4 exactly
    float m = (float)mask[t >> 5];
    float4 x = ((const float4*)g_x)[t];
    x.x *= m; x.y *= m; x.z *= m; x.w *= m;
    ((float4*)out)[t] = x;
}

// ---------------------------------------------------------------------------
// launch
// ---------------------------------------------------------------------------
extern "C" void kernel_launch(void* const* d_in, const int* in_sizes, int n_in,
                              void* d_out, int out_size) {
    (void)in_sizes; (void)n_in; (void)out_size;
    const int*   cids  = (const int*)d_in[0];
    const int*   kids  = (const int*)d_in[1];
    const int*   mask  = (const int*)d_in[2];
    const int*   eidx  = (const int*)d_in[3];
    const int*   etype = (const int*)d_in[4];
    const float* cemb  = (const float*)d_in[5];
    const float* kemb  = (const float*)d_in[6];
    const float* projW = (const float*)d_in[7];
    const float* projb = (const float*)d_in[8];
    const float* selfW = (const float*)d_in[9];
    const float* selfb = (const float*)d_in[10];
    const float* relW  = (const float*)d_in[11];
    const int* src = eidx;
    const int* dst = eidx + NE;

    const int VEC = NODES * HD / 4;  // 1048576

    static bool attr_set = false;
    if (!attr_set) {
        cudaFuncSetAttribute(k_gemm,  cudaFuncAttributeMaxDynamicSharedMemorySize, GEMM_SMEM);
        cudaFuncSetAttribute(k_embed, cudaFuncAttributeMaxDynamicSharedMemorySize, EMB_SMEM);
        attr_set = true;
    }

    // CSR build
    k_zero_cnt<<<NODES / 256, 256>>>();
    k_count<<<NE / 256, 256>>>(dst);
    k_scan<<<1, 1024>>>();
    k_fill<<<NE / 256, 256>>>(src, dst, etype);

    // weight splits + input projection
    k_split_w<<<(TOTW * HD * HD) / 256, 256>>>(relW, selfW, projW);
    k_embed<<<NODES / 128, 256, EMB_SMEM>>>(cids, kids, cemb, kemb, projb);

    for (int l = 0; l < LAYERS; l++) {
        k_gemm<<<GRID_GEMM, 256, GEMM_SMEM>>>(selfb, l);
        k_agg_update<<<NODES / 8, 256>>>();
    }

    k_output<<<VEC / 256, 256>>>(mask, (float*)d_out);
}